// round 1
// baseline (speedup 1.0000x reference)
#include <cuda_runtime.h>
#include <cuda_bf16.h>
#include <mma.h>

using namespace nvcuda;

// Problem constants
#define MB      8192      // batch rows (M)
#define DK      1024      // D = K half 1
#define HK      1024      // H = K half 2  (K_total = 2048)
#define NGATE   1024      // columns per gate block
#define BM      128       // CTA M tile
#define NJ      32        // gate-local columns per CTA (virtual N = 4*NJ = 128)
#define BK      32        // K tile
#define LDS     36        // padded smem leading dim (floats)
#define NKT     64        // 2048 / 32 k-tiles
#define THREADS 256

__device__ __forceinline__ unsigned smem_u32(const void* p) {
    return (unsigned)__cvta_generic_to_shared(p);
}
__device__ __forceinline__ void cp16(void* dst, const void* src) {
    asm volatile("cp.async.cg.shared.global [%0], [%1], 16;\n"
                 :: "r"(smem_u32(dst)), "l"(src));
}
__device__ __forceinline__ void cp_commit() { asm volatile("cp.async.commit_group;\n"); }
__device__ __forceinline__ void cp_wait0()  { asm volatile("cp.async.wait_group 0;\n"); }

__device__ __forceinline__ float sigmoidf_fast(float x) {
    return 1.0f / (1.0f + __expf(-x));
}

// Fused LSTM-cell kernel:
//   z = e_t @ W_x^T + h_prev @ W_h^T + b_x + b_h + b_extra   (computed per-tile)
//   gates (f,i,o,c) from the 4 gate blocks, cell update, write h_t and c_t.
// Each CTA: rows [m0, m0+128) x gate-local columns [j0, j0+32) of ALL 4 gates.
__global__ void __launch_bounds__(THREADS, 2)
lstm_cell_fused_kernel(const float* __restrict__ e_t,
                       const float* __restrict__ h_prev,
                       const float* __restrict__ c_prev,
                       const float* __restrict__ W_x,
                       const float* __restrict__ b_x,
                       const float* __restrict__ W_h,
                       const float* __restrict__ b_h,
                       const float* __restrict__ b_extra,
                       float* __restrict__ out)
{
    extern __shared__ float smem[];
    // Layout (floats): As0 [0,4608) As1 [4608,9216) Bs0 [9216,13824) Bs1 [13824,18432)
    // After mainloop the whole region is reused as the z tile [128][128].
    const int tid = threadIdx.x;
    const int m0  = blockIdx.y * BM;
    const int j0  = blockIdx.x * NJ;

    const int warp = tid >> 5;
    const int wm   = warp & 3;   // warp row   -> rows   wm*32 .. +32
    const int wn   = warp >> 2;  // warp col   -> vcols  wn*64 .. +64

    wmma::fragment<wmma::accumulator, 16, 16, 8, float> acc[2][4];
    #pragma unroll
    for (int i = 0; i < 2; i++)
        #pragma unroll
        for (int j = 0; j < 4; j++)
            wmma::fill_fragment(acc[i][j], 0.0f);

    // ---- tile loader (cp.async 16B) ----
    auto load_tile = [&](int kt, int buf) {
        const int  kk    = kt * BK;
        const bool first = (kk < DK);
        const float* __restrict__ Asrc = first ? e_t : h_prev;
        const float* __restrict__ Wsrc = first ? W_x : W_h;
        const int  kloc  = first ? kk : kk - DK;
        float* Ab = smem + buf * (BM * LDS);
        float* Bb = smem + 2 * (BM * LDS) + buf * (BM * LDS);
        #pragma unroll
        for (int i = 0; i < 4; i++) {
            int idx = tid + i * THREADS;      // 0..1023
            int r   = idx >> 3;               // 0..127
            int c4  = (idx & 7) * 4;          // 0,4,...,28
            // A: rows m0+r, cols kloc+c4
            cp16(Ab + r * LDS + c4,
                 Asrc + (size_t)(m0 + r) * 1024 + kloc + c4);
            // B: virtual row r -> gate g = r/32, weight row g*1024 + j0 + (r%32)
            int g  = r >> 5;
            int gr = g * NGATE + j0 + (r & 31);
            cp16(Bb + r * LDS + c4,
                 Wsrc + (size_t)gr * 1024 + kloc + c4);
        }
    };

    load_tile(0, 0);
    cp_commit();

    for (int kt = 0; kt < NKT; kt++) {
        cp_wait0();
        __syncthreads();
        if (kt + 1 < NKT) {
            load_tile(kt + 1, (kt + 1) & 1);
            cp_commit();
        }
        const float* Ab = smem + (kt & 1) * (BM * LDS);
        const float* Bb = smem + 2 * (BM * LDS) + (kt & 1) * (BM * LDS);

        #pragma unroll
        for (int ks = 0; ks < BK / 8; ks++) {
            wmma::fragment<wmma::matrix_a, 16, 16, 8, wmma::precision::tf32, wmma::row_major> af[2];
            wmma::fragment<wmma::matrix_b, 16, 16, 8, wmma::precision::tf32, wmma::col_major> bf[4];
            #pragma unroll
            for (int i = 0; i < 2; i++) {
                wmma::load_matrix_sync(af[i], Ab + (wm * 32 + i * 16) * LDS + ks * 8, LDS);
                #pragma unroll
                for (int t = 0; t < af[i].num_elements; t++)
                    af[i].x[t] = wmma::__float_to_tf32(af[i].x[t]);
            }
            #pragma unroll
            for (int j = 0; j < 4; j++) {
                wmma::load_matrix_sync(bf[j], Bb + (wn * 64 + j * 16) * LDS + ks * 8, LDS);
                #pragma unroll
                for (int t = 0; t < bf[j].num_elements; t++)
                    bf[j].x[t] = wmma::__float_to_tf32(bf[j].x[t]);
            }
            #pragma unroll
            for (int i = 0; i < 2; i++)
                #pragma unroll
                for (int j = 0; j < 4; j++)
                    wmma::mma_sync(acc[i][j], af[i], bf[j], acc[i][j]);
        }
        __syncthreads();
    }

    // ---- stage z tile in smem (reuse A/B buffers) ----
    float* zs = smem;   // [128][128] row-major
    #pragma unroll
    for (int i = 0; i < 2; i++)
        #pragma unroll
        for (int j = 0; j < 4; j++)
            wmma::store_matrix_sync(zs + (wm * 32 + i * 16) * 128 + wn * 64 + j * 16,
                                    acc[i][j], 128, wmma::mem_row_major);
    __syncthreads();

    // ---- fused epilogue ----
    const int j   = tid & 31;          // gate-local column
    const int mst = tid >> 5;          // starting row, stride 8
    const int jg  = j0 + j;            // global gate-local column

    const float bf_ = b_x[jg]             + b_h[jg]             + b_extra[jg];
    const float bi_ = b_x[NGATE + jg]     + b_h[NGATE + jg]     + b_extra[NGATE + jg];
    const float bo_ = b_x[2 * NGATE + jg] + b_h[2 * NGATE + jg] + b_extra[2 * NGATE + jg];
    const float bc_ = b_x[3 * NGATE + jg] + b_h[3 * NGATE + jg] + b_extra[3 * NGATE + jg];

    #pragma unroll
    for (int m = mst; m < BM; m += 8) {
        const int    mg = m0 + m;
        const float zf = zs[m * 128 +       j] + bf_;
        const float zi = zs[m * 128 + 32 +  j] + bi_;
        const float zo = zs[m * 128 + 64 +  j] + bo_;
        const float zc = zs[m * 128 + 96 +  j] + bc_;

        const float fg = sigmoidf_fast(zf);
        const float ig = sigmoidf_fast(zi);
        const float og = sigmoidf_fast(zo);
        const float cc = tanhf(zc);

        const float cp = c_prev[(size_t)mg * HK + jg];
        const float ct = fg * cp + ig * cc;
        const float ht = og * tanhf(ct);

        out[(size_t)mg * HK + jg]                      = ht;   // h_t
        out[(size_t)MB * HK + (size_t)mg * HK + jg]    = ct;   // c_t
    }
}

extern "C" void kernel_launch(void* const* d_in, const int* in_sizes, int n_in,
                              void* d_out, int out_size) {
    const float* e_t     = (const float*)d_in[0];
    const float* h_prev  = (const float*)d_in[1];
    const float* c_prev  = (const float*)d_in[2];
    const float* W_x     = (const float*)d_in[3];
    const float* b_x     = (const float*)d_in[4];
    const float* W_h     = (const float*)d_in[5];
    const float* b_h     = (const float*)d_in[6];
    const float* b_extra = (const float*)d_in[7];
    float* out = (float*)d_out;

    const int smem_bytes = 4 * BM * LDS * sizeof(float);   // 73728 B
    cudaFuncSetAttribute(lstm_cell_fused_kernel,
                         cudaFuncAttributeMaxDynamicSharedMemorySize, smem_bytes);

    dim3 grid(NGATE / NJ, MB / BM);   // (32, 64)
    lstm_cell_fused_kernel<<<grid, THREADS, smem_bytes>>>(
        e_t, h_prev, c_prev, W_x, b_x, W_h, b_h, b_extra, out);
}

// round 4
// speedup vs baseline: 2.8335x; 2.8335x over previous
#include <cuda_runtime.h>
#include <cstdint>

// ---------------- problem / tile constants ----------------
#define MB      8192
#define NGATE   1024
#define BM      128          // CTA M tile
#define BNV     128          // virtual N tile = 4 gates x 32 gate-local cols
#define NJ      32           // gate-local cols per CTA
#define BK      32           // K per stage (32 f32 = 128 B row)
#define NKT     64           // 2048 / 32
#define STAGES  3
#define THREADS 256

#define STAGE_FLOATS (2 * 128 * 32)          // A(128x32) + B(128x32) floats = 8192
#define SMEM_DYN     (STAGES * STAGE_FLOATS * 4)   // 98304 B

__device__ __forceinline__ uint32_t smem_u32(const void* p) {
    return (uint32_t)__cvta_generic_to_shared(p);
}
__device__ __forceinline__ void cp16(uint32_t dst, const void* src) {
    asm volatile("cp.async.cg.shared.global [%0], [%1], 16;\n" :: "r"(dst), "l"(src));
}
__device__ __forceinline__ void cp_commit() { asm volatile("cp.async.commit_group;\n"); }
template <int N>
__device__ __forceinline__ void cp_wait() {
    asm volatile("cp.async.wait_group %0;\n" :: "n"(N));
}
__device__ __forceinline__ uint32_t sw128(uint32_t off) {   // byte-offset swizzle
    return off ^ ((off >> 3) & 0x70);
}
__device__ __forceinline__ void mma_tf32(float* d, const uint32_t* a, const uint32_t* b) {
    asm volatile(
        "mma.sync.aligned.m16n8k8.row.col.f32.tf32.tf32.f32 "
        "{%0,%1,%2,%3}, {%4,%5,%6,%7}, {%8,%9}, {%0,%1,%2,%3};"
        : "+f"(d[0]), "+f"(d[1]), "+f"(d[2]), "+f"(d[3])
        : "r"(a[0]), "r"(a[1]), "r"(a[2]), "r"(a[3]), "r"(b[0]), "r"(b[1]));
}
__device__ __forceinline__ float tanh_fast(float x) {
    float y;
    asm("tanh.approx.f32 %0, %1;" : "=f"(y) : "f"(x));
    return y;
}
__device__ __forceinline__ float sigmoid_fast(float x) {
    return 0.5f * tanh_fast(0.5f * x) + 0.5f;
}

// ---------------- kernel ----------------
// z = [e_t|h_prev] @ [W_x|W_h]^T (+ biases); gates f,i,o,c; cell update.
// CTA: 128 rows x 32 gate-local cols of all 4 gates.
// Warp grid 2(m) x 4(n): warp tile 64 rows x 8 cols, n-frags strided across gates.
__global__ void __launch_bounds__(THREADS, 2)
lstm_mma_kernel(const float* __restrict__ e_t,
                const float* __restrict__ h_prev,
                const float* __restrict__ c_prev,
                const float* __restrict__ W_x,
                const float* __restrict__ b_x,
                const float* __restrict__ W_h,
                const float* __restrict__ b_h,
                const float* __restrict__ b_extra,
                float* __restrict__ out)
{
    extern __shared__ float smf[];

    const int tid  = threadIdx.x;
    const int warp = tid >> 5;
    const int lane = tid & 31;
    const int gid  = lane >> 2;     // group id 0..7
    const int tg   = lane & 3;      // thread-in-group
    const int wm   = warp >> 2;     // 0..1  -> rows wm*64
    const int wn   = warp & 3;      // 0..3  -> cols wn*8 within each gate
    const int m0   = blockIdx.y * BM;
    const int j0   = blockIdx.x * NJ;

    // ---- stage loader: k-chunk -> stage slot (cp.async, SW128 swizzle) ----
    auto load_stage = [&](int kt, int stg) {
        const int kk = kt * BK;
        const float* __restrict__ Asrc = (kk < 1024) ? e_t : h_prev;
        const float* __restrict__ Wsrc = (kk < 1024) ? W_x : W_h;
        const int kloc = kk & 1023;
        const uint32_t As = smem_u32(smf + stg * STAGE_FLOATS);
        const uint32_t Bs = As + 128 * 128;   // bytes: A tile = 16 KB
        // A: 128 rows x 128 B = 1024 x 16B chunks -> 4 per thread
        #pragma unroll
        for (int i = 0; i < 4; i++) {
            int c = tid + i * THREADS;
            int row = c >> 3, c16 = c & 7;
            cp16(As + sw128((uint32_t)(row * 128 + c16 * 16)),
                 Asrc + (size_t)(m0 + row) * 1024 + kloc + c16 * 4);
        }
        // B: 128 vrows (vr = g*32 + l) x 128 B -> 4 per thread
        #pragma unroll
        for (int i = 0; i < 4; i++) {
            int c = tid + i * THREADS;
            int vr = c >> 3, c16 = c & 7;
            int g = vr >> 5, l = vr & 31;
            cp16(Bs + sw128((uint32_t)(vr * 128 + c16 * 16)),
                 Wsrc + (size_t)(g * NGATE + j0 + l) * 1024 + kloc + c16 * 4);
        }
    };

    float acc[4][4][4];   // [m_frag][gate][elem]
    #pragma unroll
    for (int i = 0; i < 4; i++)
        #pragma unroll
        for (int g = 0; g < 4; g++)
            #pragma unroll
            for (int e = 0; e < 4; e++) acc[i][g][e] = 0.0f;

    load_stage(0, 0); cp_commit();
    load_stage(1, 1); cp_commit();

    const uint32_t key = (uint32_t)gid << 4;    // swizzle XOR key (bytes)

    for (int kt = 0; kt < NKT; kt++) {
        if (kt + 1 < NKT) cp_wait<1>(); else cp_wait<0>();
        __syncthreads();

        if (kt + 2 < NKT) {
            load_stage(kt + 2, (kt + 2) % STAGES);
            cp_commit();
        }

        const int stg = kt % STAGES;
        const float* As = smf + stg * STAGE_FLOATS;
        const float* Bs = As + 4096;   // floats

        #pragma unroll
        for (int ks = 0; ks < 4; ks++) {
            const uint32_t cx = ((uint32_t)(ks * 32 + tg * 4)) ^ key;  // byte col off
            uint32_t a[4][4], b[4][2];
            #pragma unroll
            for (int i = 0; i < 4; i++) {
                const uint32_t r0 = (uint32_t)((wm * 64 + i * 16 + gid) * 128) + cx;
                a[i][0] = __float_as_uint(As[ r0            >> 2]);
                a[i][1] = __float_as_uint(As[(r0 + 1024)    >> 2]);
                a[i][2] = __float_as_uint(As[(r0 ^ 16)      >> 2]);
                a[i][3] = __float_as_uint(As[((r0 + 1024) ^ 16) >> 2]);
            }
            #pragma unroll
            for (int g = 0; g < 4; g++) {
                const uint32_t vr = (uint32_t)((g * 32 + wn * 8 + gid) * 128) + cx;
                b[g][0] = __float_as_uint(Bs[ vr       >> 2]);
                b[g][1] = __float_as_uint(Bs[(vr ^ 16) >> 2]);
            }
            #pragma unroll
            for (int i = 0; i < 4; i++)
                #pragma unroll
                for (int g = 0; g < 4; g++)
                    mma_tf32(acc[i][g], a[i], b[g]);
        }
        __syncthreads();
    }

    // ---- fused epilogue (all in registers) ----
    const int jg = j0 + wn * 8 + tg * 2;     // gate-local col (pair base)
    float bsum[4][2];
    #pragma unroll
    for (int g = 0; g < 4; g++) {
        #pragma unroll
        for (int c = 0; c < 2; c++) {
            const int idx = g * NGATE + jg + c;
            bsum[g][c] = b_x[idx] + b_h[idx] + b_extra[idx];
        }
    }

    #pragma unroll
    for (int i = 0; i < 4; i++) {
        #pragma unroll
        for (int h = 0; h < 2; h++) {          // h=0: rows gid, h=1: gid+8
            const int mg = m0 + wm * 64 + i * 16 + gid + h * 8;
            const float2 cp = *reinterpret_cast<const float2*>(
                c_prev + (size_t)mg * 1024 + jg);
            float ht[2], ct[2];
            #pragma unroll
            for (int c = 0; c < 2; c++) {
                const int e = h * 2 + c;
                const float fg = sigmoid_fast(acc[i][0][e] + bsum[0][c]);
                const float ig = sigmoid_fast(acc[i][1][e] + bsum[1][c]);
                const float og = sigmoid_fast(acc[i][2][e] + bsum[2][c]);
                const float cc = tanh_fast   (acc[i][3][e] + bsum[3][c]);
                const float cpv = (c == 0) ? cp.x : cp.y;
                ct[c] = fg * cpv + ig * cc;
                ht[c] = og * tanh_fast(ct[c]);
            }
            *reinterpret_cast<float2*>(out + (size_t)mg * 1024 + jg) =
                make_float2(ht[0], ht[1]);
            *reinterpret_cast<float2*>(out + (size_t)MB * 1024 + (size_t)mg * 1024 + jg) =
                make_float2(ct[0], ct[1]);
        }
    }
}

// ---------------- launch ----------------
extern "C" void kernel_launch(void* const* d_in, const int* in_sizes, int n_in,
                              void* d_out, int out_size) {
    const float* e_t     = (const float*)d_in[0];
    const float* h_prev  = (const float*)d_in[1];
    const float* c_prev  = (const float*)d_in[2];
    const float* W_x     = (const float*)d_in[3];
    const float* b_x     = (const float*)d_in[4];
    const float* W_h     = (const float*)d_in[5];
    const float* b_h     = (const float*)d_in[6];
    const float* b_extra = (const float*)d_in[7];
    float* out = (float*)d_out;

    cudaFuncSetAttribute(lstm_mma_kernel,
                         cudaFuncAttributeMaxDynamicSharedMemorySize, SMEM_DYN);

    dim3 grid(NGATE / NJ, MB / BM);   // (32, 64)
    lstm_mma_kernel<<<grid, THREADS, SMEM_DYN>>>(
        e_t, h_prev, c_prev, W_x, b_x, W_h, b_h, b_extra, out);
}